// round 7
// baseline (speedup 1.0000x reference)
#include <cuda_runtime.h>

#define BB 32
#define SS 4096
#define CC 768
#define HH 12
#define DD 64
#define NCHUNK 43
#define SCHUNK 96

// ---- scratch (device globals; allocation is forbidden) ----
__device__ float g_qh[HH * DD];                               // scaled probe query
__device__ float g_wk[HH * CC];                               // folded key weights
__device__ float g_sbias[HH];                                 // qh . bk
__device__ float g_z[BB * NCHUNK * HH];                       // per-chunk expsum
__device__ float g_ypart[(size_t)BB * NCHUNK * HH * CC];      // per-chunk partial y
__device__ float g_ctx[BB * CC];                              // context (h,d flattened)

typedef unsigned long long u64;

__device__ __forceinline__ u64 pk2(float a, float b) {
    u64 r; asm("mov.b64 %0,{%1,%2};" : "=l"(r) : "f"(a), "f"(b)); return r;
}
__device__ __forceinline__ float2 up2(u64 v) {
    float2 r; asm("mov.b64 {%0,%1},%2;" : "=f"(r.x), "=f"(r.y) : "l"(v)); return r;
}
__device__ __forceinline__ void ffma2(u64& d, u64 a, u64 b) {
    asm("fma.rn.f32x2 %0,%1,%2,%0;" : "+l"(d) : "l"(a), "l"(b));
}
__device__ __forceinline__ u64 vadd2(u64 a, u64 b) {
    u64 r; asm("add.rn.f32x2 %0,%1,%2;" : "=l"(r) : "l"(a), "l"(b)); return r;
}

// ================= prep 1: qh = (probe @ Wq + bq)/8 =================
__global__ __launch_bounds__(256) void k_prep_qh(const float* __restrict__ probe,
                                                 const float* __restrict__ Wq,
                                                 const float* __restrict__ bq) {
    int h = blockIdx.x, t = threadIdx.x;
    __shared__ float red[4][DD];
    int d = t & 63, part = t >> 6;
    float a = 0.f;
    #pragma unroll 8
    for (int c = part; c < CC; c += 4)
        a = fmaf(probe[c], Wq[(size_t)c * CC + h * DD + d], a);
    red[part][d] = a;
    __syncthreads();
    if (t < DD)
        g_qh[h * DD + t] = (red[0][t] + red[1][t] + red[2][t] + red[3][t] + bq[h * DD + t]) * 0.125f;
}

// ================= prep 2: wk[h,c] = sum_d Wk[c,h,d]*qh[h,d] =================
__global__ __launch_bounds__(256) void k_prep_wk(const float* __restrict__ Wk) {
    int h = blockIdx.x, t = threadIdx.x;
    __shared__ float qs[DD];
    if (t < DD) qs[t] = g_qh[h * DD + t];
    __syncthreads();
    for (int c = t; c < CC; c += 256) {
        const float4* wr = (const float4*)(Wk + (size_t)c * CC + h * DD);
        float s = 0.f;
        #pragma unroll
        for (int j = 0; j < DD / 4; j++) {
            float4 wv = wr[j];
            const float4 qv = *(const float4*)(qs + 4 * j);
            s += wv.x * qv.x + wv.y * qv.y + wv.z * qv.z + wv.w * qv.w;
        }
        g_wk[h * CC + c] = s;
    }
}

// ================= prep 3: sbias[h] = qh[h,:].bk[h,:] =================
__global__ __launch_bounds__(384) void k_prep_sb(const float* __restrict__ bk) {
    int t = threadIdx.x, h = t >> 5, lane = t & 31;
    float a = g_qh[h * DD + lane] * bk[h * DD + lane]
            + g_qh[h * DD + 32 + lane] * bk[h * DD + 32 + lane];
    #pragma unroll
    for (int o = 16; o; o >>= 1) a += __shfl_xor_sync(~0u, a, o);
    if (lane == 0) g_sbias[h] = a;
}

// ================= fused: scores -> exp -> weighted accumulate (launch #4) ===========
// 384 threads, 2 blocks/SM (24 warps). Phase 1: warp pairs split heads 6+6,
// 4 rows/thread (acc[6][4]=48 regs). Phase 2: 4 cols/thread, 48-row halves
// (acc2[12][2]=48 regs). exp weights stored pre-duplicated (u64) in smem.
__global__ __launch_bounds__(384, 2) void k_fused(const float* __restrict__ x) {
    __shared__ __align__(16) float uS[HH * CC];      // wk (phase 1) / y stage (phase 2)
    __shared__ __align__(16) u64 scd[HH][SCHUNK];    // exp(score) duplicated, 9 KB
    __shared__ float zsh[HH];
    __shared__ float sbs[HH];

    int t = threadIdx.x, ch = blockIdx.x, b = blockIdx.y;
    int s0 = ch * SCHUNK;
    for (int i = t; i < HH * CC; i += 384) uS[i] = g_wk[i];
    if (t < HH) { sbs[t] = g_sbias[t]; zsh[t] = 0.f; }
    __syncthreads();

    int lane = t & 31, w = t >> 5, g = lane >> 3, q = lane & 7;
    const float* xb = x + (size_t)b * SS * CC;

    // ---- phase 1 ----
    {
        int p = w >> 1, h0 = (w & 1) * 6;
        int lbase = p * 16 + g;                        // local row = lbase + 4k
        const ulonglong2* xr[4];
        #pragma unroll
        for (int k = 0; k < 4; k++) {
            int row = s0 + lbase + 4 * k;
            int rc = row < SS ? row : SS - 1;
            xr[k] = (const ulonglong2*)(xb + (size_t)rc * CC) + q;
        }
        const ulonglong2* wq = (const ulonglong2*)uS + h0 * (CC / 4) + q;

        u64 acc[6][4];
        #pragma unroll
        for (int i = 0; i < 6; i++)
            #pragma unroll
            for (int k = 0; k < 4; k++) acc[i][k] = 0ull;

        #pragma unroll 4
        for (int j = 0; j < 24; j++) {
            ulonglong2 xv0 = xr[0][j * 8];
            ulonglong2 xv1 = xr[1][j * 8];
            ulonglong2 xv2 = xr[2][j * 8];
            ulonglong2 xv3 = xr[3][j * 8];
            #pragma unroll
            for (int i = 0; i < 6; i++) {
                ulonglong2 wv = wq[i * (CC / 4) + j * 8];
                ffma2(acc[i][0], xv0.x, wv.x); ffma2(acc[i][0], xv0.y, wv.y);
                ffma2(acc[i][1], xv1.x, wv.x); ffma2(acc[i][1], xv1.y, wv.y);
                ffma2(acc[i][2], xv2.x, wv.x); ffma2(acc[i][2], xv2.y, wv.y);
                ffma2(acc[i][3], xv3.x, wv.x); ffma2(acc[i][3], xv3.y, wv.y);
            }
        }
        #pragma unroll
        for (int i = 0; i < 6; i++) {
            float zt = 0.f;
            #pragma unroll
            for (int k = 0; k < 4; k++) {
                u64 v = acc[i][k];
                v = vadd2(v, __shfl_xor_sync(0xffffffffu, v, 4));
                v = vadd2(v, __shfl_xor_sync(0xffffffffu, v, 2));
                v = vadd2(v, __shfl_xor_sync(0xffffffffu, v, 1));
                if (q == 0) {
                    int lr = lbase + 4 * k;
                    float2 f = up2(v);
                    float e = (s0 + lr < SS) ? __expf(f.x + f.y + sbs[h0 + i]) : 0.f;
                    scd[h0 + i][lr] = pk2(e, e);
                    zt += e;
                }
            }
            float zq = (q == 0) ? zt : 0.f;
            zq += __shfl_xor_sync(0xffffffffu, zq, 8);
            zq += __shfl_xor_sync(0xffffffffu, zq, 16);
            if (lane == 0) atomicAdd(&zsh[h0 + i], zq);
        }
    }
    __syncthreads();
    if (t < HH) g_z[(b * NCHUNK + ch) * HH + t] = zsh[t];

    // ---- phase 2: y_part = sum_s p[h][s] * x[s,:] ----
    int half = t / 192, u = t - half * 192;            // cols 4u..4u+3
    int bs = half * 48;
    int rem = SS - (s0 + bs);
    int slim = rem < 0 ? 0 : (rem > 48 ? 48 : rem);    // always even
    const float* xp = xb + (size_t)(s0 + bs) * CC + 4 * u;

    u64 acc2[HH][2];
    #pragma unroll
    for (int h = 0; h < HH; h++) { acc2[h][0] = 0ull; acc2[h][1] = 0ull; }

    #pragma unroll 2
    for (int s2 = 0; s2 < slim / 2; s2++) {
        ulonglong2 x0 = *(const ulonglong2*)(xp + (size_t)(2 * s2) * CC);
        ulonglong2 x1 = *(const ulonglong2*)(xp + (size_t)(2 * s2 + 1) * CC);
        #pragma unroll
        for (int h = 0; h < HH; h++) {
            ulonglong2 pv = *(const ulonglong2*)&scd[h][bs + 2 * s2];
            ffma2(acc2[h][0], pv.x, x0.x); ffma2(acc2[h][1], pv.x, x0.y);
            ffma2(acc2[h][0], pv.y, x1.x); ffma2(acc2[h][1], pv.y, x1.y);
        }
    }

    // half 1 stages into uS (wk no longer needed); half 0 merges and writes
    __syncthreads();
    if (half == 1) {
        #pragma unroll
        for (int h = 0; h < HH; h++) {
            float2 l0 = up2(acc2[h][0]), l1 = up2(acc2[h][1]);
            *(float4*)(uS + h * CC + 4 * u) = make_float4(l0.x, l0.y, l1.x, l1.y);
        }
    }
    __syncthreads();
    if (half == 0) {
        float* yp = g_ypart + ((size_t)(b * NCHUNK + ch)) * (HH * CC);
        #pragma unroll
        for (int h = 0; h < HH; h++) {
            float2 l0 = up2(acc2[h][0]), l1 = up2(acc2[h][1]);
            float4 sv = *(const float4*)(uS + h * CC + 4 * u);
            *(float4*)(yp + h * CC + 4 * u) =
                make_float4(l0.x + sv.x, l0.y + sv.y, l1.x + sv.z, l1.y + sv.w);
        }
    }
}

// ================= combine + ctx: y = sum(ypart)/Z, ctx = y @ Wv + bv =================
__global__ __launch_bounds__(256) void k_combctx(const float* __restrict__ Wv,
                                                 const float* __restrict__ bv) {
    int b = blockIdx.x, h = blockIdx.y, t = threadIdx.x;
    __shared__ float ys[CC];
    __shared__ float red[4][DD];
    __shared__ float invZ_s;

    if (t < 32) {
        float z = 0.f;
        for (int c2 = t; c2 < NCHUNK; c2 += 32) z += g_z[(b * NCHUNK + c2) * HH + h];
        #pragma unroll
        for (int o = 16; o; o >>= 1) z += __shfl_xor_sync(~0u, z, o);
        if (t == 0) invZ_s = 1.f / z;
    }
    __syncthreads();
    float invZ = invZ_s;

    #pragma unroll
    for (int i = 0; i < 3; i++) {
        int c = t + 256 * i;
        const float* base = g_ypart + (size_t)b * NCHUNK * HH * CC + h * CC + c;
        float a0 = 0.f, a1 = 0.f, a2 = 0.f, a3 = 0.f;
        #pragma unroll 4
        for (int chn = 0; chn < NCHUNK - 3; chn += 4) {
            a0 += base[(size_t)chn * HH * CC];
            a1 += base[(size_t)(chn + 1) * HH * CC];
            a2 += base[(size_t)(chn + 2) * HH * CC];
            a3 += base[(size_t)(chn + 3) * HH * CC];
        }
        for (int chn = NCHUNK & ~3; chn < NCHUNK; chn++)
            a0 += base[(size_t)chn * HH * CC];
        ys[c] = ((a0 + a1) + (a2 + a3)) * invZ;
    }
    __syncthreads();

    int d = t & 63, part = t >> 6;
    const float* wp = Wv + h * DD + d;
    float a0 = 0.f, a1 = 0.f;
    #pragma unroll 8
    for (int c = part; c < CC; c += 8) {
        a0 = fmaf(ys[c],     wp[(size_t)c * CC],       a0);
        a1 = fmaf(ys[c + 4], wp[(size_t)(c + 4) * CC], a1);
    }
    red[part][d] = a0 + a1;
    __syncthreads();
    if (t < DD)
        g_ctx[b * CC + h * DD + t] =
            red[0][t] + red[1][t] + red[2][t] + red[3][t] + bv[h * DD + t];
}

// ================= out: out[b,c'] = ctx[b,:] @ Wo + bo =================
__global__ __launch_bounds__(192) void k_out(const float* __restrict__ Wo,
                                             const float* __restrict__ bo,
                                             float* __restrict__ out) {
    int b = blockIdx.x, part = blockIdx.y, t = threadIdx.x;
    __shared__ float cs[CC];
    for (int i = t; i < CC; i += 192) cs[i] = g_ctx[b * CC + i];
    __syncthreads();
    int cp = part * 192 + t;
    const float* wp = Wo + cp;
    float a0 = 0.f, a1 = 0.f, a2 = 0.f, a3 = 0.f;
    #pragma unroll 8
    for (int o = 0; o < CC; o += 4) {
        a0 = fmaf(cs[o],     wp[(size_t)o * CC],       a0);
        a1 = fmaf(cs[o + 1], wp[(size_t)(o + 1) * CC], a1);
        a2 = fmaf(cs[o + 2], wp[(size_t)(o + 2) * CC], a2);
        a3 = fmaf(cs[o + 3], wp[(size_t)(o + 3) * CC], a3);
    }
    out[(size_t)b * CC + cp] = (a0 + a1) + (a2 + a3) + bo[cp];
}

extern "C" void kernel_launch(void* const* d_in, const int* in_sizes, int n_in,
                              void* d_out, int out_size) {
    const float* x     = (const float*)d_in[0];
    const float* probe = (const float*)d_in[1];
    const float* Wq    = (const float*)d_in[2];
    const float* bq    = (const float*)d_in[3];
    const float* Wk    = (const float*)d_in[4];
    const float* bk    = (const float*)d_in[5];
    const float* Wv    = (const float*)d_in[6];
    const float* bv    = (const float*)d_in[7];
    const float* Wo    = (const float*)d_in[8];
    const float* bo    = (const float*)d_in[9];
    float* out = (float*)d_out;

    k_prep_qh<<<HH, 256>>>(probe, Wq, bq);          // #1
    k_prep_wk<<<HH, 256>>>(Wk);                     // #2
    k_prep_sb<<<1, 384>>>(bk);                      // #3
    k_fused<<<dim3(NCHUNK, BB), 384>>>(x);          // #4  <- profiled
    k_combctx<<<dim3(BB, HH), 256>>>(Wv, bv);       // #5
    k_out<<<dim3(BB, 4), 192>>>(Wo, bo, out);       // #6
}